// round 14
// baseline (speedup 1.0000x reference)
#include <cuda_runtime.h>
#include <cstdint>

// Conv2d 3x3: x[32,128,56,56] f32 * w[256,128,3,3] f32 -> out[32,256,56,56]
// tf32 mma.sync implicit GEMM, CUTLASS-shaped tiles:
// CTA = M128 oc x N128 flat px, 4 warps, warp tile M64xN64 (128 acc regs), 2 CTAs/SM.
// K=1152 in 72 k16 chunks. A: fragment-packed tf32 (prep), LDG.128 + reg ping-pong.
// B: 4B zfill cp.async im2col staging, 4-stage ring, swizzled, LDSM consumption.

static __device__ __forceinline__ uint32_t smem_u32(const void* p) {
    uint32_t a;
    asm("{ .reg .u64 t; cvta.to.shared.u64 t, %1; cvt.u32.u64 %0, t; }" : "=r"(a) : "l"(p));
    return a;
}
static __device__ __forceinline__ uint32_t totf(float f) {
    float r; asm("cvt.rna.tf32.f32 %0, %1;" : "=f"(r) : "f"(f));
    return __float_as_uint(r);
}

#define LDSM4(r, addr) \
    asm volatile("ldmatrix.sync.aligned.m8n8.x4.shared.b16 {%0,%1,%2,%3}, [%4];" \
        : "=r"((r)[0]), "=r"((r)[1]), "=r"((r)[2]), "=r"((r)[3]) : "r"(addr))

#define MMA1688(d, a, b0, b1) \
    asm volatile("mma.sync.aligned.m16n8k8.row.col.f32.tf32.tf32.f32 " \
        "{%0,%1,%2,%3}, {%4,%5,%6,%7}, {%8,%9}, {%0,%1,%2,%3};" \
        : "+f"((d)[0]), "+f"((d)[1]), "+f"((d)[2]), "+f"((d)[3]) \
        : "r"((a)[0]), "r"((a)[1]), "r"((a)[2]), "r"((a)[3]), "r"(b0), "r"(b1))

static __device__ __forceinline__ void cpa4(uint32_t dst, const float* src, int ok) {
    asm volatile(
        "{\n\t.reg .pred p;\n\t.reg .b32 sz;\n\t"
        "setp.ne.b32 p, %2, 0;\n\t"
        "selp.b32 sz, 4, 0, p;\n\t"
        "cp.async.ca.shared.global [%0], [%1], 4, sz;\n\t}"
        :: "r"(dst), "l"(src), "r"(ok) : "memory");
}
#define CP_COMMIT() asm volatile("cp.async.commit_group;" ::: "memory")
#define CP_WAIT2()  asm volatile("cp.async.wait_group 2;"  ::: "memory")

#define ROWB 80u               // B smem row stride (4 x 16B data + 16B pad)
#define BTILE (128u * ROWB)    // 10240 B per stage (128 pixel rows)
#define NSTAGE 4

// A fragments: [kb(144)][oc16(16)][lane(32)][4], tf32 bits, ldmatrix.x4 reg order.
__device__ float g_prep[144 * 16 * 32 * 4];
// x pre-rounded to tf32 bits.
__device__ float g_xtf[32 * 128 * 56 * 56];

// ---- merged prep: blocks [0,1152) pack weights, [1152, 13696) round x ----
__global__ void __launch_bounds__(256)
prep_all(const float* __restrict__ w, const float* __restrict__ x) {
    if (blockIdx.x < 1152) {
        int idx  = blockIdx.x * 256 + threadIdx.x;
        int j    = idx & 3;
        int lane = (idx >> 2) & 31;
        int oc16 = (idx >> 7) & 15;
        int kb   = idx >> 11;
        int row  = oc16 * 16 + (lane >> 2) + ((j & 1) ? 8 : 0);
        int col  = kb * 8 + (lane & 3) + ((j & 2) ? 4 : 0);
        g_prep[idx] = __uint_as_float(totf(w[(size_t)row * 1152 + col]));
    } else {
        size_t i = ((size_t)(blockIdx.x - 1152) * 256 + threadIdx.x) * 4;
        float4 v = *reinterpret_cast<const float4*>(x + i);
        float4 o;
        o.x = __uint_as_float(totf(v.x));
        o.y = __uint_as_float(totf(v.y));
        o.z = __uint_as_float(totf(v.z));
        o.w = __uint_as_float(totf(v.w));
        *reinterpret_cast<float4*>(g_xtf + i) = o;
    }
}

__global__ void __launch_bounds__(128, 2)
conv3x3_tf32_hmma11(float* __restrict__ out)
{
    __shared__ int   s_tbl[1152];
    __shared__ float s_B[NSTAGE][128 * 20];   // 4 x 10240 B

    const int tid  = threadIdx.x;
    const int lane = tid & 31;
    const int wid  = tid >> 5;                // 0..3
    const int warpM = wid & 1;                // 64 oc each (within 128-oc CTA block)
    const int warpN = wid >> 1;               // 64 px each

    const int gp0 = blockIdx.x << 7;          // 128 flat pixels per CTA
    const int ocb = blockIdx.y << 7;          // oc block 0 / 128

    for (int k = tid; k < 1152; k += 128) {
        int ic = k / 9;
        int r9 = k - ic * 9;
        int kh = r9 / 3;
        int kw = r9 - kh * 3;
        s_tbl[k] = (((ic * 3136) + (kh - 1) * 56 + (kw - 1)) << 4) | r9;
    }

    // ---- B staging geometry: thread owns pixel row pl = tid, all 16 k of the chunk ----
    const int pl  = tid;
    const int gp  = gp0 + pl;
    const int img = gp / 3136;
    const int p   = gp - img * 3136;
    const int r   = p / 56;
    const int c   = p - r * 56;
    unsigned mask9 = 0;
    #pragma unroll
    for (int dh = -1; dh <= 1; dh++)
        #pragma unroll
        for (int dw = -1; dw <= 1; dw++)
            if ((unsigned)(r + dh) < 56u && (unsigned)(c + dw) < 56u)
                mask9 |= 1u << ((dh + 1) * 3 + (dw + 1));
    const float* pbase = g_xtf + (size_t)img * 401408 + p;

    const uint32_t bS = smem_u32(s_B[0]);
    const uint32_t swz = (uint32_t)((pl >> 3) & 3);          // store-side swizzle
    const uint32_t rowbase = (uint32_t)pl * ROWB;

    // ---- LDSM offsets (read-side swizzle matches store): ----
    // rows r0+jj*16, col16 q = ((lane>>3)&1) + 2s, sw = (2jj + (lane>>4)) & 3
    const uint32_t row0    = (uint32_t)((warpN << 6) + (lane & 7) + ((lane >> 4) << 3));
    const uint32_t colbase = (uint32_t)(((lane >> 3) & 1) << 4);
    uint32_t boff[2][4];   // [s][jj]
    #pragma unroll
    for (int s = 0; s < 2; s++)
        #pragma unroll
        for (int jj = 0; jj < 4; jj++) {
            uint32_t sw = (uint32_t)((2 * jj + (lane >> 4)) & 3) << 4;
            boff[s][jj] = (row0 + (uint32_t)(jj * 16)) * ROWB
                        + (((colbase | (uint32_t)(s << 5))) ^ sw);
        }

    // A fragment base: oc16 tiles (ocb/16 + warpM*4 + i)
    const float4* aP = reinterpret_cast<const float4*>(g_prep)
                     + (size_t)((blockIdx.y << 3) + (warpM << 2)) * 32 + lane;

    float acc[4][8][4];
    #pragma unroll
    for (int i = 0; i < 4; i++)
        #pragma unroll
        for (int j = 0; j < 8; j++)
            #pragma unroll
            for (int q = 0; q < 4; q++) acc[i][j][q] = 0.0f;

    __syncthreads();   // table ready

    // ---- prologue: stage chunks 0..2 ----
    #pragma unroll
    for (int pre = 0; pre < 3; pre++) {
        const uint32_t stg = bS + (uint32_t)pre * BTILE + rowbase;
        #pragma unroll
        for (int q = 0; q < 4; q++) {
            int4 e = *reinterpret_cast<const int4*>(&s_tbl[pre * 16 + (q << 2)]);
            uint32_t d = stg + (((uint32_t)q ^ swz) << 4);
            int ee[4] = {e.x, e.y, e.z, e.w};
            #pragma unroll
            for (int wd = 0; wd < 4; wd++) {
                int ok = (mask9 >> (ee[wd] & 15)) & 1;
                cpa4(d + 4u * wd, pbase + (ok ? (ee[wd] >> 4) : 0), ok);
            }
        }
        CP_COMMIT();
    }

    // ---- prologue: A regs for kb=0 ----
    uint32_t af[2][4][4];
    #pragma unroll
    for (int i = 0; i < 4; i++) {
        float4 av = __ldg(aP + (size_t)i * 32);
        af[0][i][0] = __float_as_uint(av.x); af[0][i][1] = __float_as_uint(av.y);
        af[0][i][2] = __float_as_uint(av.z); af[0][i][3] = __float_as_uint(av.w);
    }

    #pragma unroll 1
    for (int ch = 0; ch < 72; ch++) {
        CP_WAIT2();
        __syncthreads();

        // ---- stage chunk ch+3 ----
        if (ch + 3 < 72) {
            const uint32_t stg = bS + (uint32_t)(((ch + 3) & 3) * BTILE) + rowbase;
            #pragma unroll
            for (int q = 0; q < 4; q++) {
                int4 e = *reinterpret_cast<const int4*>(&s_tbl[(ch + 3) * 16 + (q << 2)]);
                uint32_t d = stg + (((uint32_t)q ^ swz) << 4);
                int ee[4] = {e.x, e.y, e.z, e.w};
                #pragma unroll
                for (int wd = 0; wd < 4; wd++) {
                    int ok = (mask9 >> (ee[wd] & 15)) & 1;
                    cpa4(d + 4u * wd, pbase + (ok ? (ee[wd] >> 4) : 0), ok);
                }
            }
        }
        CP_COMMIT();

        const uint32_t bBuf = bS + (uint32_t)((ch & 3) * BTILE);
        // ---- compute: 2 k8 steps; per-step B hoist (4 LDSM.x4) + A ping-pong ----
        #pragma unroll
        for (int s = 0; s < 2; s++) {
            const int kb  = ch * 2 + s;
            const int cur = kb & 1;
            uint32_t bf[4][4];
            #pragma unroll
            for (int jj = 0; jj < 4; jj++)
                LDSM4(bf[jj], bBuf + boff[s][jj]);
            if (kb + 1 < 144) {
                #pragma unroll
                for (int i = 0; i < 4; i++) {
                    float4 av = __ldg(aP + ((size_t)(kb + 1) * 16 + i) * 32);
                    af[cur ^ 1][i][0] = __float_as_uint(av.x);
                    af[cur ^ 1][i][1] = __float_as_uint(av.y);
                    af[cur ^ 1][i][2] = __float_as_uint(av.z);
                    af[cur ^ 1][i][3] = __float_as_uint(av.w);
                }
            }
            #pragma unroll
            for (int i = 0; i < 4; i++)
                #pragma unroll
                for (int j = 0; j < 8; j++)
                    MMA1688(acc[i][j], af[cur][i],
                            bf[j >> 1][(j & 1) * 2], bf[j >> 1][(j & 1) * 2 + 1]);
        }
    }

    // ---- epilogue: STG.64 per fragment pair ----
    #pragma unroll
    for (int i = 0; i < 4; i++) {
        const int mrow = ocb + warpM * 64 + i * 16 + (lane >> 2);
        #pragma unroll
        for (int j = 0; j < 8; j++) {
            int nl  = warpN * 64 + j * 8 + 2 * (lane & 3);
            int gp2 = gp0 + nl;
            int im2 = gp2 / 3136;
            int pp  = gp2 - im2 * 3136;
            float* o0 = out + ((size_t)im2 * 256 + mrow) * 3136 + pp;
            *reinterpret_cast<float2*>(o0)            = make_float2(acc[i][j][0], acc[i][j][1]);
            *reinterpret_cast<float2*>(o0 + 8 * 3136) = make_float2(acc[i][j][2], acc[i][j][3]);
        }
    }
}

extern "C" void kernel_launch(void* const* d_in, const int* in_sizes, int n_in,
                              void* d_out, int out_size) {
    const float* x = (const float*)d_in[0];   // [32,128,56,56]
    const float* w = (const float*)d_in[1];   // [256,128,3,3]
    float* out = (float*)d_out;               // [32,256,56,56]

    prep_all<<<13696, 256>>>(w, x);           // weights-pack + x tf32-round, ONE launch
    conv3x3_tf32_hmma11<<<dim3(784, 2), 128>>>(out);
}

// round 15
// speedup vs baseline: 1.2215x; 1.2215x over previous
#include <cuda_runtime.h>
#include <cstdint>

// Conv2d 3x3: x[32,128,56,56] f32 * w[256,128,3,3] f32 -> out[32,256,56,56]
// tf32 mma.sync implicit GEMM. CTA: M=256 oc x N=64 flat px, K=1152 (72 k16 chunks).
// EXACT round-6 main kernel (best measured main, ~349us): per-step LDSM, per-step
// A register ping-pong, 4B zfill cp.async B staging, 4-stage ring, 2 CTAs/SM.
// Preps merged into ONE launch (faster + keeps ncu window on the main kernel).

static __device__ __forceinline__ uint32_t smem_u32(const void* p) {
    uint32_t a;
    asm("{ .reg .u64 t; cvta.to.shared.u64 t, %1; cvt.u32.u64 %0, t; }" : "=r"(a) : "l"(p));
    return a;
}
static __device__ __forceinline__ uint32_t totf(float f) {
    float r; asm("cvt.rna.tf32.f32 %0, %1;" : "=f"(r) : "f"(f));
    return __float_as_uint(r);
}

#define LDSM4(r, addr) \
    asm volatile("ldmatrix.sync.aligned.m8n8.x4.shared.b16 {%0,%1,%2,%3}, [%4];" \
        : "=r"((r)[0]), "=r"((r)[1]), "=r"((r)[2]), "=r"((r)[3]) : "r"(addr))

#define MMA1688(d, a, b0, b1) \
    asm volatile("mma.sync.aligned.m16n8k8.row.col.f32.tf32.tf32.f32 " \
        "{%0,%1,%2,%3}, {%4,%5,%6,%7}, {%8,%9}, {%0,%1,%2,%3};" \
        : "+f"((d)[0]), "+f"((d)[1]), "+f"((d)[2]), "+f"((d)[3]) \
        : "r"((a)[0]), "r"((a)[1]), "r"((a)[2]), "r"((a)[3]), "r"(b0), "r"(b1))

static __device__ __forceinline__ void cpa4(uint32_t dst, const float* src, int ok) {
    asm volatile(
        "{\n\t.reg .pred p;\n\t.reg .b32 sz;\n\t"
        "setp.ne.b32 p, %2, 0;\n\t"
        "selp.b32 sz, 4, 0, p;\n\t"
        "cp.async.ca.shared.global [%0], [%1], 4, sz;\n\t}"
        :: "r"(dst), "l"(src), "r"(ok) : "memory");
}
#define CP_COMMIT() asm volatile("cp.async.commit_group;" ::: "memory")
#define CP_WAIT2()  asm volatile("cp.async.wait_group 2;"  ::: "memory")

#define ROWB 80u              // B smem row stride (16 k * 4B + pad)
#define BTILE (64u * ROWB)    // 5120 B per stage
#define NSTAGE 4

// A fragments: [kb(144)][oc16(16)][lane(32)][4], tf32 bits, ldmatrix.x4 reg order.
__device__ float g_prep[144 * 16 * 32 * 4];
// x pre-rounded to tf32 bits.
__device__ float g_xtf[32 * 128 * 56 * 56];

// ---- merged prep: blocks [0,1152) pack weights, [1152, 13696) round x ----
__global__ void __launch_bounds__(256)
prep_all(const float* __restrict__ w, const float* __restrict__ x) {
    if (blockIdx.x < 1152) {
        int idx  = blockIdx.x * 256 + threadIdx.x;
        int j    = idx & 3;
        int lane = (idx >> 2) & 31;
        int oc16 = (idx >> 7) & 15;
        int kb   = idx >> 11;
        int row  = oc16 * 16 + (lane >> 2) + ((j & 1) ? 8 : 0);
        int col  = kb * 8 + (lane & 3) + ((j & 2) ? 4 : 0);
        g_prep[idx] = __uint_as_float(totf(w[(size_t)row * 1152 + col]));
    } else {
        size_t i = ((size_t)(blockIdx.x - 1152) * 256 + threadIdx.x) * 4;
        float4 v = *reinterpret_cast<const float4*>(x + i);
        float4 o;
        o.x = __uint_as_float(totf(v.x));
        o.y = __uint_as_float(totf(v.y));
        o.z = __uint_as_float(totf(v.z));
        o.w = __uint_as_float(totf(v.w));
        *reinterpret_cast<float4*>(g_xtf + i) = o;
    }
}

__global__ void __launch_bounds__(256, 2)
conv3x3_tf32_final(float* __restrict__ out)
{
    __shared__ int   s_tbl[1152];
    __shared__ float s_B[NSTAGE][64 * 20];

    const int tid  = threadIdx.x;
    const int lane = tid & 31;
    const int wid  = tid >> 5;
    const int warpM = wid & 3;            // 64 oc each
    const int warpN = wid >> 2;           // 32 px each

    const int gp0 = blockIdx.x << 6;

    for (int k = tid; k < 1152; k += 256) {
        int ic = k / 9;
        int r9 = k - ic * 9;
        int kh = r9 / 3;
        int kw = r9 - kh * 3;
        s_tbl[k] = (((ic * 3136) + (kh - 1) * 56 + (kw - 1)) << 4) | r9;
    }

    // ---- B staging geometry: warp = 32 consecutive px, one k-quad ----
    const int pl   = ((wid & 1) << 5) + lane;
    const int quad = wid >> 1;
    const int gp   = gp0 + pl;
    const int img  = gp / 3136;
    const int p    = gp - img * 3136;
    const int r    = p / 56;
    const int c    = p - r * 56;
    unsigned mask9 = 0;
    #pragma unroll
    for (int dh = -1; dh <= 1; dh++)
        #pragma unroll
        for (int dw = -1; dw <= 1; dw++)
            if ((unsigned)(r + dh) < 56u && (unsigned)(c + dw) < 56u)
                mask9 |= 1u << ((dh + 1) * 3 + (dw + 1));
    const float* pbase = g_xtf + (size_t)img * 401408 + p;

    const uint32_t bS = smem_u32(s_B[0]);
    const uint32_t sts_off = (uint32_t)pl * ROWB + (uint32_t)(quad << 4);
    const uint32_t boff = (uint32_t)((warpN << 5) + (lane & 7) + ((lane >> 4) << 3)) * ROWB
                        + (uint32_t)(((lane >> 3) & 1) << 4);

    const float4* aP = reinterpret_cast<const float4*>(g_prep) + (size_t)(warpM * 4) * 32 + lane;

    float acc[4][4][4];
    #pragma unroll
    for (int i = 0; i < 4; i++)
        #pragma unroll
        for (int j = 0; j < 4; j++)
            #pragma unroll
            for (int q = 0; q < 4; q++) acc[i][j][q] = 0.0f;

    __syncthreads();   // table ready

    // ---- prologue: stage chunks 0..2 ----
    #pragma unroll
    for (int pre = 0; pre < 3; pre++) {
        int4 e = *reinterpret_cast<const int4*>(&s_tbl[pre * 16 + (quad << 2)]);
        uint32_t d = bS + (uint32_t)pre * BTILE + sts_off;
        int ee[4] = {e.x, e.y, e.z, e.w};
        #pragma unroll
        for (int j = 0; j < 4; j++) {
            int ok = (mask9 >> (ee[j] & 15)) & 1;
            cpa4(d + 4u * j, pbase + (ok ? (ee[j] >> 4) : 0), ok);
        }
        CP_COMMIT();
    }

    // ---- prologue: A regs for kb=0 ----
    uint32_t af[2][4][4];
    #pragma unroll
    for (int i = 0; i < 4; i++) {
        float4 av = __ldg(aP + (size_t)i * 32);
        af[0][i][0] = __float_as_uint(av.x); af[0][i][1] = __float_as_uint(av.y);
        af[0][i][2] = __float_as_uint(av.z); af[0][i][3] = __float_as_uint(av.w);
    }

    #pragma unroll 1
    for (int ch = 0; ch < 72; ch++) {
        CP_WAIT2();
        __syncthreads();

        // ---- stage chunk ch+3 ----
        if (ch + 3 < 72) {
            int4 e = *reinterpret_cast<const int4*>(&s_tbl[(ch + 3) * 16 + (quad << 2)]);
            uint32_t d = bS + (uint32_t)(((ch + 3) & 3) * BTILE) + sts_off;
            int ee[4] = {e.x, e.y, e.z, e.w};
            #pragma unroll
            for (int j = 0; j < 4; j++) {
                int ok = (mask9 >> (ee[j] & 15)) & 1;
                cpa4(d + 4u * j, pbase + (ok ? (ee[j] >> 4) : 0), ok);
            }
        }
        CP_COMMIT();

        // ---- compute: 2 k8 steps, per-step LDSM + A ping-pong (round-6 exact) ----
        const uint32_t bBuf = bS + (uint32_t)((ch & 3) * BTILE);
        #pragma unroll
        for (int s = 0; s < 2; s++) {
            const int kb  = ch * 2 + s;
            const int cur = kb & 1;
            if (kb + 1 < 144) {
                #pragma unroll
                for (int i = 0; i < 4; i++) {
                    float4 av = __ldg(aP + ((size_t)(kb + 1) * 16 + i) * 32);
                    af[cur ^ 1][i][0] = __float_as_uint(av.x);
                    af[cur ^ 1][i][1] = __float_as_uint(av.y);
                    af[cur ^ 1][i][2] = __float_as_uint(av.z);
                    af[cur ^ 1][i][3] = __float_as_uint(av.w);
                }
            }
            uint32_t bf[2][4];
            #pragma unroll
            for (int jj = 0; jj < 2; jj++)
                LDSM4(bf[jj], bBuf + boff + (uint32_t)(jj * 16) * ROWB + (uint32_t)(s * 32));
            #pragma unroll
            for (int i = 0; i < 4; i++)
                #pragma unroll
                for (int j = 0; j < 4; j++)
                    MMA1688(acc[i][j], af[cur][i],
                            bf[j >> 1][(j & 1) * 2], bf[j >> 1][(j & 1) * 2 + 1]);
        }
    }

    // ---- epilogue: STG.64 per fragment pair ----
    #pragma unroll
    for (int i = 0; i < 4; i++) {
        const int mrow = warpM * 64 + i * 16 + (lane >> 2);
        #pragma unroll
        for (int j = 0; j < 4; j++) {
            int nl  = warpN * 32 + j * 8 + 2 * (lane & 3);
            int gp2 = gp0 + nl;
            int im2 = gp2 / 3136;
            int pp  = gp2 - im2 * 3136;
            float* o0 = out + ((size_t)im2 * 256 + mrow) * 3136 + pp;
            *reinterpret_cast<float2*>(o0)            = make_float2(acc[i][j][0], acc[i][j][1]);
            *reinterpret_cast<float2*>(o0 + 8 * 3136) = make_float2(acc[i][j][2], acc[i][j][3]);
        }
    }
}

extern "C" void kernel_launch(void* const* d_in, const int* in_sizes, int n_in,
                              void* d_out, int out_size) {
    const float* x = (const float*)d_in[0];   // [32,128,56,56]
    const float* w = (const float*)d_in[1];   // [256,128,3,3]
    float* out = (float*)d_out;               // [32,256,56,56]

    prep_all<<<13696, 256>>>(w, x);           // weights-pack + x tf32-round, ONE launch
    conv3x3_tf32_final<<<1568, 256>>>(out);
}

// round 16
// speedup vs baseline: 1.2405x; 1.0155x over previous
#include <cuda_runtime.h>
#include <cstdint>

// Conv2d 3x3: x[32,128,56,56] f32 * w[256,128,3,3] f32 -> out[32,256,56,56]
// tf32 mma.sync implicit GEMM. CTA: M=256 oc x N=64 flat px, K=1152 (72 k16 chunks).
// Round-15 base (352us main) + ONE change: ANTI-PHASED chunk body.
//   warps 0-3: stage(ch+3) -> compute(ch);  warps 4-7: compute(ch) -> stage(ch+3).
// Each SMSP (wid%4) gets one warp of each phase -> staging (LSU) overlaps MMA bursts
// instead of the barrier-lockstep [all stage][all compute] pattern.
// A: fragment-packed tf32 in gmem, LDG.128 + register ping-pong.
// B: 4B zfill cp.async im2col staging, 4-stage ring, LDSM consumption. 2 CTAs/SM.

static __device__ __forceinline__ uint32_t smem_u32(const void* p) {
    uint32_t a;
    asm("{ .reg .u64 t; cvta.to.shared.u64 t, %1; cvt.u32.u64 %0, t; }" : "=r"(a) : "l"(p));
    return a;
}
static __device__ __forceinline__ uint32_t totf(float f) {
    float r; asm("cvt.rna.tf32.f32 %0, %1;" : "=f"(r) : "f"(f));
    return __float_as_uint(r);
}

#define LDSM4(r, addr) \
    asm volatile("ldmatrix.sync.aligned.m8n8.x4.shared.b16 {%0,%1,%2,%3}, [%4];" \
        : "=r"((r)[0]), "=r"((r)[1]), "=r"((r)[2]), "=r"((r)[3]) : "r"(addr))

#define MMA1688(d, a, b0, b1) \
    asm volatile("mma.sync.aligned.m16n8k8.row.col.f32.tf32.tf32.f32 " \
        "{%0,%1,%2,%3}, {%4,%5,%6,%7}, {%8,%9}, {%0,%1,%2,%3};" \
        : "+f"((d)[0]), "+f"((d)[1]), "+f"((d)[2]), "+f"((d)[3]) \
        : "r"((a)[0]), "r"((a)[1]), "r"((a)[2]), "r"((a)[3]), "r"(b0), "r"(b1))

static __device__ __forceinline__ void cpa4(uint32_t dst, const float* src, int ok) {
    asm volatile(
        "{\n\t.reg .pred p;\n\t.reg .b32 sz;\n\t"
        "setp.ne.b32 p, %2, 0;\n\t"
        "selp.b32 sz, 4, 0, p;\n\t"
        "cp.async.ca.shared.global [%0], [%1], 4, sz;\n\t}"
        :: "r"(dst), "l"(src), "r"(ok) : "memory");
}
#define CP_COMMIT() asm volatile("cp.async.commit_group;" ::: "memory")
#define CP_WAIT2()  asm volatile("cp.async.wait_group 2;"  ::: "memory")

#define ROWB 80u              // B smem row stride (16 k * 4B + pad)
#define BTILE (64u * ROWB)    // 5120 B per stage
#define NSTAGE 4

// A fragments: [kb(144)][oc16(16)][lane(32)][4], tf32 bits, ldmatrix.x4 reg order.
__device__ float g_prep[144 * 16 * 32 * 4];
// x pre-rounded to tf32 bits.
__device__ float g_xtf[32 * 128 * 56 * 56];

// ---- merged prep: blocks [0,1152) pack weights, [1152, 13696) round x ----
__global__ void __launch_bounds__(256)
prep_all(const float* __restrict__ w, const float* __restrict__ x) {
    if (blockIdx.x < 1152) {
        int idx  = blockIdx.x * 256 + threadIdx.x;
        int j    = idx & 3;
        int lane = (idx >> 2) & 31;
        int oc16 = (idx >> 7) & 15;
        int kb   = idx >> 11;
        int row  = oc16 * 16 + (lane >> 2) + ((j & 1) ? 8 : 0);
        int col  = kb * 8 + (lane & 3) + ((j & 2) ? 4 : 0);
        g_prep[idx] = __uint_as_float(totf(w[(size_t)row * 1152 + col]));
    } else {
        size_t i = ((size_t)(blockIdx.x - 1152) * 256 + threadIdx.x) * 4;
        float4 v = *reinterpret_cast<const float4*>(x + i);
        float4 o;
        o.x = __uint_as_float(totf(v.x));
        o.y = __uint_as_float(totf(v.y));
        o.z = __uint_as_float(totf(v.z));
        o.w = __uint_as_float(totf(v.w));
        *reinterpret_cast<float4*>(g_xtf + i) = o;
    }
}

__global__ void __launch_bounds__(256, 2)
conv3x3_tf32_ap(float* __restrict__ out)
{
    __shared__ int   s_tbl[1152];
    __shared__ float s_B[NSTAGE][64 * 20];

    const int tid  = threadIdx.x;
    const int lane = tid & 31;
    const int wid  = tid >> 5;
    const int warpM = wid & 3;            // 64 oc each
    const int warpN = wid >> 2;           // 32 px each

    const int gp0 = blockIdx.x << 6;

    for (int k = tid; k < 1152; k += 256) {
        int ic = k / 9;
        int r9 = k - ic * 9;
        int kh = r9 / 3;
        int kw = r9 - kh * 3;
        s_tbl[k] = (((ic * 3136) + (kh - 1) * 56 + (kw - 1)) << 4) | r9;
    }

    // ---- B staging geometry: warp = 32 consecutive px, one k-quad ----
    const int pl   = ((wid & 1) << 5) + lane;
    const int quad = wid >> 1;
    const int gp   = gp0 + pl;
    const int img  = gp / 3136;
    const int p    = gp - img * 3136;
    const int r    = p / 56;
    const int c    = p - r * 56;
    unsigned mask9 = 0;
    #pragma unroll
    for (int dh = -1; dh <= 1; dh++)
        #pragma unroll
        for (int dw = -1; dw <= 1; dw++)
            if ((unsigned)(r + dh) < 56u && (unsigned)(c + dw) < 56u)
                mask9 |= 1u << ((dh + 1) * 3 + (dw + 1));
    const float* pbase = g_xtf + (size_t)img * 401408 + p;

    const uint32_t bS = smem_u32(s_B[0]);
    const uint32_t sts_off = (uint32_t)pl * ROWB + (uint32_t)(quad << 4);
    const uint32_t boff = (uint32_t)((warpN << 5) + (lane & 7) + ((lane >> 4) << 3)) * ROWB
                        + (uint32_t)(((lane >> 3) & 1) << 4);

    const float4* aP = reinterpret_cast<const float4*>(g_prep) + (size_t)(warpM * 4) * 32 + lane;

    float acc[4][4][4];
    #pragma unroll
    for (int i = 0; i < 4; i++)
        #pragma unroll
        for (int j = 0; j < 4; j++)
            #pragma unroll
            for (int q = 0; q < 4; q++) acc[i][j][q] = 0.0f;

    __syncthreads();   // table ready

    // ---- prologue: stage chunks 0..2 ----
    #pragma unroll
    for (int pre = 0; pre < 3; pre++) {
        int4 e = *reinterpret_cast<const int4*>(&s_tbl[pre * 16 + (quad << 2)]);
        uint32_t d = bS + (uint32_t)pre * BTILE + sts_off;
        int ee[4] = {e.x, e.y, e.z, e.w};
        #pragma unroll
        for (int j = 0; j < 4; j++) {
            int ok = (mask9 >> (ee[j] & 15)) & 1;
            cpa4(d + 4u * j, pbase + (ok ? (ee[j] >> 4) : 0), ok);
        }
        CP_COMMIT();
    }

    // ---- prologue: A regs for kb=0 ----
    uint32_t af[2][4][4];
    #pragma unroll
    for (int i = 0; i < 4; i++) {
        float4 av = __ldg(aP + (size_t)i * 32);
        af[0][i][0] = __float_as_uint(av.x); af[0][i][1] = __float_as_uint(av.y);
        af[0][i][2] = __float_as_uint(av.z); af[0][i][3] = __float_as_uint(av.w);
    }

    // stage chunk ch3 into its ring buffer, then commit (one group per call)
    auto stage_chunk = [&](int ch3) {
        if (ch3 < 72) {
            int4 e = *reinterpret_cast<const int4*>(&s_tbl[ch3 * 16 + (quad << 2)]);
            uint32_t d = bS + (uint32_t)((ch3 & 3) * BTILE) + sts_off;
            int ee[4] = {e.x, e.y, e.z, e.w};
            #pragma unroll
            for (int j = 0; j < 4; j++) {
                int ok = (mask9 >> (ee[j] & 15)) & 1;
                cpa4(d + 4u * j, pbase + (ok ? (ee[j] >> 4) : 0), ok);
            }
        }
        CP_COMMIT();
    };

    // compute chunk ch: 2 k8 steps, per-step LDSM + A ping-pong (round-15 exact)
    auto compute_chunk = [&](int ch) {
        const uint32_t bBuf = bS + (uint32_t)((ch & 3) * BTILE);
        #pragma unroll
        for (int s = 0; s < 2; s++) {
            const int kb  = ch * 2 + s;
            const int cur = kb & 1;
            if (kb + 1 < 144) {
                #pragma unroll
                for (int i = 0; i < 4; i++) {
                    float4 av = __ldg(aP + ((size_t)(kb + 1) * 16 + i) * 32);
                    af[cur ^ 1][i][0] = __float_as_uint(av.x);
                    af[cur ^ 1][i][1] = __float_as_uint(av.y);
                    af[cur ^ 1][i][2] = __float_as_uint(av.z);
                    af[cur ^ 1][i][3] = __float_as_uint(av.w);
                }
            }
            uint32_t bf[2][4];
            #pragma unroll
            for (int jj = 0; jj < 2; jj++)
                LDSM4(bf[jj], bBuf + boff + (uint32_t)(jj * 16) * ROWB + (uint32_t)(s * 32));
            #pragma unroll
            for (int i = 0; i < 4; i++)
                #pragma unroll
                for (int j = 0; j < 4; j++)
                    MMA1688(acc[i][j], af[cur][i],
                            bf[j >> 1][(j & 1) * 2], bf[j >> 1][(j & 1) * 2 + 1]);
        }
    };

    const bool early = (wid < 4);   // one early + one late warp per SMSP (wid%4)

    #pragma unroll 1
    for (int ch = 0; ch < 72; ch++) {
        CP_WAIT2();
        __syncthreads();
        if (early) {
            stage_chunk(ch + 3);    // LSU first...
            compute_chunk(ch);      // ...then tensor
        } else {
            compute_chunk(ch);      // tensor first...
            stage_chunk(ch + 3);    // ...then LSU
        }
    }

    // ---- epilogue: STG.64 per fragment pair ----
    #pragma unroll
    for (int i = 0; i < 4; i++) {
        const int mrow = warpM * 64 + i * 16 + (lane >> 2);
        #pragma unroll
        for (int j = 0; j < 4; j++) {
            int nl  = warpN * 32 + j * 8 + 2 * (lane & 3);
            int gp2 = gp0 + nl;
            int im2 = gp2 / 3136;
            int pp  = gp2 - im2 * 3136;
            float* o0 = out + ((size_t)im2 * 256 + mrow) * 3136 + pp;
            *reinterpret_cast<float2*>(o0)            = make_float2(acc[i][j][0], acc[i][j][1]);
            *reinterpret_cast<float2*>(o0 + 8 * 3136) = make_float2(acc[i][j][2], acc[i][j][3]);
        }
    }
}

extern "C" void kernel_launch(void* const* d_in, const int* in_sizes, int n_in,
                              void* d_out, int out_size) {
    const float* x = (const float*)d_in[0];   // [32,128,56,56]
    const float* w = (const float*)d_in[1];   // [256,128,3,3]
    float* out = (float*)d_out;               // [32,256,56,56]

    prep_all<<<13696, 256>>>(w, x);           // weights-pack + x tf32-round, ONE launch
    conv3x3_tf32_ap<<<1568, 256>>>(out);
}